// round 9
// baseline (speedup 1.0000x reference)
#include <cuda_runtime.h>
#include <cuda_bf16.h>

// ---------------------------------------------------------------------------
// KAN feature extractor, GB300 sm_103a.
//   layer1: KANconv3x3 (1->2) on 28x28 + maxpool2 -> (B,2,14,14)
//   layer2: KANconv3x3 (2->2) on 14x14 + maxpool2 -> (B,2,7,7) -> (B,98)
//
// Uniform cubic B-spline, knots g[j]=(j-3)*0.4-1.0. For x in interval
// i (in [0,10]) the 4 nonzero bases (t = local param):
//   b0=(1-t)^3/6, b1=(3t^3-6t^2+4)/6, b2=1-b0-b1-b3, b3=t^3/6
// Weights stored as float4 per (interval, column): one LDS.128 per dot.
// ---------------------------------------------------------------------------

#define MAX_B 4096
__device__ float g_mid[MAX_B * 2 * 14 * 14];   // (B,2,14,14)

__device__ __forceinline__ float silu_f(float v) {
    return __fdividef(v, 1.0f + __expf(-v));
}

// interval index i (clamped to [0,10]) + 4 basis weights (zeroed if OOB)
__device__ __forceinline__ void bspline_w4(float x, int& i,
                                           float& b0, float& b1,
                                           float& b2, float& b3) {
    float u  = (x + 2.2f) * 2.5f;
    float fi = floorf(u);
    int   ii = (int)fi;
    float t  = u - fi;
    bool  inb = (ii >= 0) && (ii <= 10);
    if (!inb) { ii = 0; t = 0.0f; }
    float t2 = t * t;
    float t3 = t2 * t;
    b3 = t3 * (1.0f / 6.0f);
    b0 = fmaf(0.5f, t2 - t, 1.0f / 6.0f) - b3;          // (1-t)^3/6
    b1 = fmaf(0.5f, t3, 2.0f / 3.0f) - t2;              // (3t^3-6t^2+4)/6
    b2 = 1.0f - b0 - b1 - b3;                           // partition of unity
    if (!inb) { b0 = b1 = b2 = b3 = 0.0f; }
    i = ii;
}

// ---------------------------------------------------------------------------
// Layer 1: Cin=1, Cout=2. One thread per pooled cell (b,h2,w2), both o.
// w4sh[(i*9+k)*2+o] = float4 of the 4 active spline weights for interval i.
// ---------------------------------------------------------------------------
__global__ void __launch_bounds__(256)
kan_layer1(const float* __restrict__ x,        // (B,1,28,28)
           const float* __restrict__ base_w,   // (2,1,9)
           const float* __restrict__ spline_w, // (2,1,9,8)
           const float* __restrict__ scaler,   // (2,1,9)
           int B) {
    __shared__ float4 w4sh[11 * 9 * 2];
    __shared__ float  bwsh[18];

    int tid = threadIdx.x;
    for (int idx = tid; idx < 11 * 9 * 2; idx += blockDim.x) {
        int o  = idx & 1;
        int ik = idx >> 1;
        int i  = ik / 9;
        int k  = ik - i * 9;
        int col = o * 9 + k;
        float sc = scaler[col];
        float4 w;
        float* wp = (float*)&w;
#pragma unroll
        for (int m = 0; m < 4; m++) {
            int g = i - 3 + m;
            wp[m] = (g >= 0 && g <= 7) ? spline_w[col * 8 + g] * sc : 0.0f;
        }
        w4sh[idx] = w;
    }
    for (int idx = tid; idx < 18; idx += blockDim.x) bwsh[idx] = base_w[idx];
    __syncthreads();

    int t = blockIdx.x * blockDim.x + tid;
    if (t >= B * 196) return;
    int b   = t / 196;
    int rem = t - b * 196;
    int h2  = rem / 14;
    int w2  = rem - h2 * 14;

    const float* xb = x + b * 784;
    int h0 = 2 * h2 - 1;
    int w0 = 2 * w2 - 1;

    float val[4][4];
#pragma unroll
    for (int r = 0; r < 4; r++) {
        int  hh    = h0 + r;
        bool rowok = (hh >= 0) && (hh < 28);
#pragma unroll
        for (int c = 0; c < 4; c++) {
            int  ww = w0 + c;
            bool ok = rowok && (ww >= 0) && (ww < 28);
            val[r][c] = ok ? xb[hh * 28 + ww] : 0.0f;
        }
    }

    float acc[2][2][2];  // [dy][dx][o]
#pragma unroll
    for (int dy = 0; dy < 2; dy++)
#pragma unroll
        for (int dx = 0; dx < 2; dx++)
#pragma unroll
            for (int o = 0; o < 2; o++) acc[dy][dx][o] = 0.0f;

#pragma unroll
    for (int r = 0; r < 4; r++) {
#pragma unroll
        for (int c = 0; c < 4; c++) {
            float v = val[r][c];
            float s = silu_f(v);
            int   i;
            float b0, b1, b2, b3;
            bspline_w4(v, i, b0, b1, b2, b3);
            const float4* wrow = &w4sh[i * 18];      // i*9*2
#pragma unroll
            for (int dy = 0; dy < 2; dy++) {
                if (r - dy < 0 || r - dy > 2) continue;
#pragma unroll
                for (int dx = 0; dx < 2; dx++) {
                    if (c - dx < 0 || c - dx > 2) continue;
                    int k = (r - dy) * 3 + (c - dx);
#pragma unroll
                    for (int o = 0; o < 2; o++) {
                        float4 w = wrow[k * 2 + o];
                        float a = acc[dy][dx][o];
                        a = fmaf(bwsh[o * 9 + k], s, a);
                        a = fmaf(w.x, b0, a);
                        a = fmaf(w.y, b1, a);
                        a = fmaf(w.z, b2, a);
                        a = fmaf(w.w, b3, a);
                        acc[dy][dx][o] = a;
                    }
                }
            }
        }
    }

#pragma unroll
    for (int o = 0; o < 2; o++) {
        float m = fmaxf(fmaxf(acc[0][0][o], acc[0][1][o]),
                        fmaxf(acc[1][0][o], acc[1][1][o]));
        g_mid[b * 392 + o * 196 + h2 * 14 + w2] = m;
    }
}

// ---------------------------------------------------------------------------
// Layer 2: Cin=2, Cout=2 on 14x14. One thread per (pooled cell, o) —
// doubles thread count (grid was occupancy-limited at 392 blocks).
// w4sh[(i*18 + ci*9 + k)*2 + o]
// ---------------------------------------------------------------------------
__global__ void __launch_bounds__(256)
kan_layer2(const float* __restrict__ base_w,   // (2,2,9)
           const float* __restrict__ spline_w, // (2,2,9,8)
           const float* __restrict__ scaler,   // (2,2,9)
           float* __restrict__ out,            // (B,98)
           int B) {
    __shared__ float4 w4sh[11 * 18 * 2];
    __shared__ float  bwsh[36];

    int tid = threadIdx.x;
    for (int idx = tid; idx < 11 * 18 * 2; idx += blockDim.x) {
        int o   = idx & 1;
        int icc = idx >> 1;
        int i   = icc / 18;
        int cc  = icc - i * 18;       // ci*9+k
        int col = o * 18 + cc;
        float sc = scaler[col];
        float4 w;
        float* wp = (float*)&w;
#pragma unroll
        for (int m = 0; m < 4; m++) {
            int g = i - 3 + m;
            wp[m] = (g >= 0 && g <= 7) ? spline_w[col * 8 + g] * sc : 0.0f;
        }
        w4sh[idx] = w;
    }
    for (int idx = tid; idx < 36; idx += blockDim.x) bwsh[idx] = base_w[idx];
    __syncthreads();

    int t = blockIdx.x * blockDim.x + tid;
    if (t >= B * 98) return;
    int o   = t & 1;
    int u   = t >> 1;
    int b   = u / 49;
    int rem = u - b * 49;
    int h2  = rem / 7;
    int w2  = rem - h2 * 7;

    int h0 = 2 * h2 - 1;
    int w0 = 2 * w2 - 1;

    float acc[2][2];  // [dy][dx], this thread's o only
#pragma unroll
    for (int dy = 0; dy < 2; dy++)
#pragma unroll
        for (int dx = 0; dx < 2; dx++) acc[dy][dx] = 0.0f;

#pragma unroll
    for (int ci = 0; ci < 2; ci++) {
        const float* mb = g_mid + b * 392 + ci * 196;
        float val[4][4];
#pragma unroll
        for (int r = 0; r < 4; r++) {
            int  hh    = h0 + r;
            bool rowok = (hh >= 0) && (hh < 14);
#pragma unroll
            for (int c = 0; c < 4; c++) {
                int  ww = w0 + c;
                bool ok = rowok && (ww >= 0) && (ww < 14);
                val[r][c] = ok ? mb[hh * 14 + ww] : 0.0f;
            }
        }
#pragma unroll
        for (int r = 0; r < 4; r++) {
#pragma unroll
            for (int c = 0; c < 4; c++) {
                float v = val[r][c];
                float s = silu_f(v);
                int   i;
                float b0, b1, b2, b3;
                bspline_w4(v, i, b0, b1, b2, b3);
                const float4* wrow = &w4sh[(i * 18 + ci * 9) * 2 + o];
#pragma unroll
                for (int dy = 0; dy < 2; dy++) {
                    if (r - dy < 0 || r - dy > 2) continue;
#pragma unroll
                    for (int dx = 0; dx < 2; dx++) {
                        if (c - dx < 0 || c - dx > 2) continue;
                        int k = (r - dy) * 3 + (c - dx);
                        float4 w = wrow[k * 2];
                        float a = acc[dy][dx];
                        a = fmaf(bwsh[o * 18 + ci * 9 + k], s, a);
                        a = fmaf(w.x, b0, a);
                        a = fmaf(w.y, b1, a);
                        a = fmaf(w.z, b2, a);
                        a = fmaf(w.w, b3, a);
                        acc[dy][dx] = a;
                    }
                }
            }
        }
    }

    float m = fmaxf(fmaxf(acc[0][0], acc[0][1]),
                    fmaxf(acc[1][0], acc[1][1]));
    out[b * 98 + o * 49 + h2 * 7 + w2] = m;
}

extern "C" void kernel_launch(void* const* d_in, const int* in_sizes, int n_in,
                              void* d_out, int out_size) {
    const float *x = 0, *bw1 = 0, *sw1 = 0, *sc1 = 0, *bw2 = 0, *sw2 = 0, *sc2 = 0;
    if (n_in == 7) {
        for (int i = 0; i < n_in; i++) {
            int s = in_sizes[i];
            const float* p = (const float*)d_in[i];
            if      (s == 144) sw1 = p;
            else if (s == 288) sw2 = p;
            else if (s == 18)  { if (!bw1) bw1 = p; else sc1 = p; }
            else if (s == 36)  { if (!bw2) bw2 = p; else sc2 = p; }
            else               x = p;
        }
    }
    if (!x || !bw1 || !sw1 || !sc1 || !bw2 || !sw2 || !sc2) {
        x   = (const float*)d_in[0];
        bw1 = (const float*)d_in[1];
        sw1 = (const float*)d_in[2];
        sc1 = (const float*)d_in[3];
        bw2 = (const float*)d_in[4];
        sw2 = (const float*)d_in[5];
        sc2 = (const float*)d_in[6];
    }
    float* out = (float*)d_out;

    int B = out_size / 98;
    if (B > MAX_B) B = MAX_B;

    int n1 = B * 196;
    int n2 = B * 98;
    kan_layer1<<<(n1 + 255) / 256, 256>>>(x, bw1, sw1, sc1, B);
    kan_layer2<<<(n2 + 255) / 256, 256>>>(bw2, sw2, sc2, out, B);
}

// round 10
// speedup vs baseline: 1.5090x; 1.5090x over previous
#include <cuda_runtime.h>
#include <cuda_bf16.h>

// ---------------------------------------------------------------------------
// KAN feature extractor, GB300 sm_103a.
//   layer1: KANconv3x3 (1->2) on 28x28 + maxpool2 -> (B,2,14,14)
//   layer2: KANconv3x3 (2->2) on 14x14 + maxpool2 -> (B,2,7,7) -> (B,98)
//
// Spline path: uniform cubic B-spline, knots g[j]=(j-3)*0.4-1.0. Per
// (interval i, column) we precompute CUBIC POLY COEFFS c0..c3 of
// p(t) = sum_g w_g B_g(x), t = local param, via the uniform B-spline matrix:
//   c0=(w0+4w1+w2)/6, c1=(w2-w0)/2, c2=(w0-2w1+w2)/2, c3=(-w0+3w1-3w2+w3)/6
// Row 11 of the table is all-zero (gather indices OOB) -> used for x outside
// [-2.2,2.2): branch-free zero spline, matching the reference.
// Both output channels are packed into f32x2 (fma.rn.f32x2).
// ---------------------------------------------------------------------------

#define MAX_B 4096
__device__ float g_mid[MAX_B * 2 * 14 * 14];   // (B,2,14,14)

typedef unsigned long long u64;

__device__ __forceinline__ u64 pack2(float lo, float hi) {
    u64 d;
    asm("mov.b64 %0, {%1, %2};" : "=l"(d) : "f"(lo), "f"(hi));
    return d;
}
__device__ __forceinline__ void unpack2(u64 v, float& lo, float& hi) {
    asm("mov.b64 {%0, %1}, %2;" : "=f"(lo), "=f"(hi) : "l"(v));
}
__device__ __forceinline__ u64 ffma2(u64 a, u64 b, u64 c) {
    u64 d;
    asm("fma.rn.f32x2 %0, %1, %2, %3;" : "=l"(d) : "l"(a), "l"(b), "l"(c));
    return d;
}
__device__ __forceinline__ u64 fadd2(u64 a, u64 b) {
    u64 d;
    asm("add.rn.f32x2 %0, %1, %2;" : "=l"(d) : "l"(a), "l"(b));
    return d;
}

__device__ __forceinline__ float silu_f(float v) {
    return __fdividef(v, 1.0f + __expf(-v));
}

// interval index (11 = zero row if OOB) and local parameter t
__device__ __forceinline__ void interval_t(float x, int& i, float& t) {
    float u  = (x + 2.2f) * 2.5f;
    float fi = floorf(u);
    int   ii = (int)fi;
    t = u - fi;
    i = (ii >= 0 && ii <= 10) ? ii : 11;
}

// build poly-coeff float2 row entry for one (i, col): both o packed.
// wsrc layout: [col][8] with col = o*NC+cc ; sc likewise.
template <int NC>
__device__ __forceinline__ float2 coef_entry(const float* __restrict__ sw,
                                             const float* __restrict__ sc,
                                             int i, int cc, int m) {
    float c[2];
#pragma unroll
    for (int o = 0; o < 2; o++) {
        int col = o * NC + cc;
        float s = sc[col];
        float w[4];
#pragma unroll
        for (int g = 0; g < 4; g++) {
            int gg = i - 3 + g;
            w[g] = (gg >= 0 && gg <= 7) ? sw[col * 8 + gg] * s : 0.0f;
        }
        float cm;
        if      (m == 0) cm = (w[0] + 4.0f * w[1] + w[2]) * (1.0f / 6.0f);
        else if (m == 1) cm = (w[2] - w[0]) * 0.5f;
        else if (m == 2) cm = (w[0] - 2.0f * w[1] + w[2]) * 0.5f;
        else             cm = (-w[0] + 3.0f * w[1] - 3.0f * w[2] + w[3]) * (1.0f / 6.0f);
        c[o] = cm;
    }
    return make_float2(c[0], c[1]);
}

// ---------------------------------------------------------------------------
// Layer 1: Cin=1, Cout=2. Thread = pooled cell, both o packed in f32x2.
// csh row = interval i (12 rows), 9*4 entries, padded to 37 float2.
// ---------------------------------------------------------------------------
#define ROW1 37
__global__ void __launch_bounds__(256)
kan_layer1(const float* __restrict__ x,        // (B,1,28,28)
           const float* __restrict__ base_w,   // (2,1,9)
           const float* __restrict__ spline_w, // (2,1,9,8)
           const float* __restrict__ scaler,   // (2,1,9)
           int B) {
    __shared__ float2 csh[12 * ROW1];
    __shared__ float2 bwsh[9];

    int tid = threadIdx.x;
    for (int idx = tid; idx < 12 * 36; idx += blockDim.x) {
        int i  = idx / 36;
        int r  = idx - i * 36;
        int cc = r >> 2;          // k
        int m  = r & 3;
        csh[i * ROW1 + r] = coef_entry<9>(spline_w, scaler, i, cc, m);
    }
    for (int idx = tid; idx < 9; idx += blockDim.x)
        bwsh[idx] = make_float2(base_w[idx], base_w[9 + idx]);
    __syncthreads();

    int t = blockIdx.x * blockDim.x + tid;
    if (t >= B * 196) return;
    int b   = t / 196;
    int rem = t - b * 196;
    int h2  = rem / 14;
    int w2  = rem - h2 * 14;

    const float* xb = x + b * 784;
    int h0 = 2 * h2 - 1;
    int w0 = 2 * w2 - 1;

    u64 bwp[9];
#pragma unroll
    for (int k = 0; k < 9; k++)
        bwp[k] = *reinterpret_cast<const u64*>(&bwsh[k]);

    float val[4][4];
#pragma unroll
    for (int r = 0; r < 4; r++) {
        int  hh    = h0 + r;
        bool rowok = (hh >= 0) && (hh < 28);
#pragma unroll
        for (int c = 0; c < 4; c++) {
            int  ww = w0 + c;
            bool ok = rowok && (ww >= 0) && (ww < 28);
            val[r][c] = ok ? xb[hh * 28 + ww] : 0.0f;
        }
    }

    u64 acc[2][2];
#pragma unroll
    for (int dy = 0; dy < 2; dy++)
#pragma unroll
        for (int dx = 0; dx < 2; dx++) acc[dy][dx] = pack2(0.0f, 0.0f);

#pragma unroll
    for (int r = 0; r < 4; r++) {
#pragma unroll
        for (int c = 0; c < 4; c++) {
            float v = val[r][c];
            float s = silu_f(v);
            int   i;
            float tt;
            interval_t(v, i, tt);
            u64 t2 = pack2(tt, tt);
            u64 s2 = pack2(s, s);
            const u64* row = reinterpret_cast<const u64*>(&csh[i * ROW1]);
#pragma unroll
            for (int dy = 0; dy < 2; dy++) {
                if (r - dy < 0 || r - dy > 2) continue;
#pragma unroll
                for (int dx = 0; dx < 2; dx++) {
                    if (c - dx < 0 || c - dx > 2) continue;
                    int k = (r - dy) * 3 + (c - dx);
                    u64 c0 = row[k * 4 + 0];
                    u64 c1 = row[k * 4 + 1];
                    u64 c2 = row[k * 4 + 2];
                    u64 c3 = row[k * 4 + 3];
                    u64 p  = ffma2(c3, t2, c2);
                    p      = ffma2(p,  t2, c1);
                    p      = ffma2(p,  t2, c0);
                    u64 a  = acc[dy][dx];
                    a      = ffma2(bwp[k], s2, a);
                    a      = fadd2(a, p);
                    acc[dy][dx] = a;
                }
            }
        }
    }

    float a00, a01, a10, a11, b00, b01, b10, b11;
    unpack2(acc[0][0], a00, b00);
    unpack2(acc[0][1], a01, b01);
    unpack2(acc[1][0], a10, b10);
    unpack2(acc[1][1], a11, b11);
    float m0 = fmaxf(fmaxf(a00, a01), fmaxf(a10, a11));
    float m1 = fmaxf(fmaxf(b00, b01), fmaxf(b10, b11));
    g_mid[b * 392 + h2 * 14 + w2]       = m0;
    g_mid[b * 392 + 196 + h2 * 14 + w2] = m1;
}

// ---------------------------------------------------------------------------
// Layer 2: Cin=2, Cout=2 on 14x14. Thread = pooled cell, o packed.
// csh row = 18*4 entries padded to 73 float2.
// ---------------------------------------------------------------------------
#define ROW2 73
__global__ void __launch_bounds__(256)
kan_layer2(const float* __restrict__ base_w,   // (2,2,9)
           const float* __restrict__ spline_w, // (2,2,9,8)
           const float* __restrict__ scaler,   // (2,2,9)
           float* __restrict__ out,            // (B,98)
           int B) {
    __shared__ float2 csh[12 * ROW2];
    __shared__ float2 bwsh[18];

    int tid = threadIdx.x;
    for (int idx = tid; idx < 12 * 72; idx += blockDim.x) {
        int i  = idx / 72;
        int r  = idx - i * 72;
        int cc = r >> 2;          // ci*9+k
        int m  = r & 3;
        csh[i * ROW2 + r] = coef_entry<18>(spline_w, scaler, i, cc, m);
    }
    for (int idx = tid; idx < 18; idx += blockDim.x)
        bwsh[idx] = make_float2(base_w[idx], base_w[18 + idx]);
    __syncthreads();

    int t = blockIdx.x * blockDim.x + tid;
    if (t >= B * 49) return;
    int b   = t / 49;
    int rem = t - b * 49;
    int h2  = rem / 7;
    int w2  = rem - h2 * 7;

    int h0 = 2 * h2 - 1;
    int w0 = 2 * w2 - 1;

    u64 bwp[18];
#pragma unroll
    for (int k = 0; k < 18; k++)
        bwp[k] = *reinterpret_cast<const u64*>(&bwsh[k]);

    u64 acc[2][2];
#pragma unroll
    for (int dy = 0; dy < 2; dy++)
#pragma unroll
        for (int dx = 0; dx < 2; dx++) acc[dy][dx] = pack2(0.0f, 0.0f);

#pragma unroll
    for (int ci = 0; ci < 2; ci++) {
        const float* mb = g_mid + b * 392 + ci * 196;
        float val[4][4];
#pragma unroll
        for (int r = 0; r < 4; r++) {
            int  hh    = h0 + r;
            bool rowok = (hh >= 0) && (hh < 14);
#pragma unroll
            for (int c = 0; c < 4; c++) {
                int  ww = w0 + c;
                bool ok = rowok && (ww >= 0) && (ww < 14);
                val[r][c] = ok ? mb[hh * 14 + ww] : 0.0f;
            }
        }
#pragma unroll
        for (int r = 0; r < 4; r++) {
#pragma unroll
            for (int c = 0; c < 4; c++) {
                float v = val[r][c];
                float s = silu_f(v);
                int   i;
                float tt;
                interval_t(v, i, tt);
                u64 t2 = pack2(tt, tt);
                u64 s2 = pack2(s, s);
                const u64* row = reinterpret_cast<const u64*>(&csh[i * ROW2]) + ci * 36;
#pragma unroll
                for (int dy = 0; dy < 2; dy++) {
                    if (r - dy < 0 || r - dy > 2) continue;
#pragma unroll
                    for (int dx = 0; dx < 2; dx++) {
                        if (c - dx < 0 || c - dx > 2) continue;
                        int k = (r - dy) * 3 + (c - dx);
                        u64 c0 = row[k * 4 + 0];
                        u64 c1 = row[k * 4 + 1];
                        u64 c2 = row[k * 4 + 2];
                        u64 c3 = row[k * 4 + 3];
                        u64 p  = ffma2(c3, t2, c2);
                        p      = ffma2(p,  t2, c1);
                        p      = ffma2(p,  t2, c0);
                        u64 a  = acc[dy][dx];
                        a      = ffma2(bwp[ci * 9 + k], s2, a);
                        a      = fadd2(a, p);
                        acc[dy][dx] = a;
                    }
                }
            }
        }
    }

    float a00, a01, a10, a11, b00, b01, b10, b11;
    unpack2(acc[0][0], a00, b00);
    unpack2(acc[0][1], a01, b01);
    unpack2(acc[1][0], a10, b10);
    unpack2(acc[1][1], a11, b11);
    float m0 = fmaxf(fmaxf(a00, a01), fmaxf(a10, a11));
    float m1 = fmaxf(fmaxf(b00, b01), fmaxf(b10, b11));
    out[b * 98 + h2 * 7 + w2]      = m0;
    out[b * 98 + 49 + h2 * 7 + w2] = m1;
}

extern "C" void kernel_launch(void* const* d_in, const int* in_sizes, int n_in,
                              void* d_out, int out_size) {
    const float *x = 0, *bw1 = 0, *sw1 = 0, *sc1 = 0, *bw2 = 0, *sw2 = 0, *sc2 = 0;
    if (n_in == 7) {
        for (int i = 0; i < n_in; i++) {
            int s = in_sizes[i];
            const float* p = (const float*)d_in[i];
            if      (s == 144) sw1 = p;
            else if (s == 288) sw2 = p;
            else if (s == 18)  { if (!bw1) bw1 = p; else sc1 = p; }
            else if (s == 36)  { if (!bw2) bw2 = p; else sc2 = p; }
            else               x = p;
        }
    }
    if (!x || !bw1 || !sw1 || !sc1 || !bw2 || !sw2 || !sc2) {
        x   = (const float*)d_in[0];
        bw1 = (const float*)d_in[1];
        sw1 = (const float*)d_in[2];
        sc1 = (const float*)d_in[3];
        bw2 = (const float*)d_in[4];
        sw2 = (const float*)d_in[5];
        sc2 = (const float*)d_in[6];
    }
    float* out = (float*)d_out;

    int B = out_size / 98;
    if (B > MAX_B) B = MAX_B;

    int n1 = B * 196;
    int n2 = B * 49;
    kan_layer1<<<(n1 + 255) / 256, 256>>>(x, bw1, sw1, sc1, B);
    kan_layer2<<<(n2 + 255) / 256, 256>>>(bw2, sw2, sc2, out, B);
}